// round 3
// baseline (speedup 1.0000x reference)
#include <cuda_runtime.h>
#include <cuda_bf16.h>

#define NN      100000
#define NE      3200000
#define FIN     16
#define HID     64
#define NG      64
#define SCAN_BS 1024
#define NB_SCAN ((NN + SCAN_BS - 1) / SCAN_BS)   // 98

// ---------------- scratch (static device memory; no allocations) ----------------
__device__ float g_degw[NN];
__device__ int   g_cnt[NN];
__device__ float g_dinv[NN];
__device__ int   g_rowptr[NN + 1];
__device__ int   g_woff[NN];
__device__ int2  g_csr[NE];            // {src, weight bits}
__device__ float g_s1[(size_t)NN * HID];
__device__ float g_s2[(size_t)NN * HID];
__device__ int   g_bsum[NB_SCAN];
__device__ int   g_boff[NB_SCAN];
__device__ float g_gsum[NG * HID];
__device__ int   g_gcnt[NG];
__device__ int   g_mode64;             // 1 if index tensors are int64, 0 if int32

__device__ __forceinline__ float sigm(float x) { return 1.0f / (1.0f + __expf(-x)); }

// read element i of an index array that is either int32 or int64 (little-endian)
__device__ __forceinline__ int idx_read(const int* p, int i, int mode64) {
    return mode64 ? p[2 * i] : p[i];
}

// ---------------- dtype probe ----------------
// If edge_index is int64, every odd 32-bit word is a zero high-word (ids < 2^31).
// If int32, odd words are random node ids -> OR over 4096 of them is ~surely nonzero.
__global__ void k_probe(const int* __restrict__ ei32) {
    __shared__ int sh[256];
    int tid = threadIdx.x;
    int acc = 0;
    for (int i = tid; i < 4096; i += 256) acc |= ei32[2 * i + 1];
    sh[tid] = acc;
    __syncthreads();
    for (int off = 128; off > 0; off >>= 1) {
        if (tid < off) sh[tid] |= sh[tid + off];
        __syncthreads();
    }
    if (tid == 0) g_mode64 = (sh[0] == 0) ? 1 : 0;
}

// ---------------- setup ----------------
__global__ void k_zero() {
    int i = blockIdx.x * blockDim.x + threadIdx.x;
    if (i < NN) { g_degw[i] = 0.0f; g_cnt[i] = 0; }
    if (i < NG * HID) g_gsum[i] = 0.0f;
    if (i < NG) g_gcnt[i] = 0;
}

__global__ void k_deg(const int* __restrict__ ei, const float* __restrict__ ew) {
    int e = blockIdx.x * blockDim.x + threadIdx.x;
    int m = g_mode64;
    if (e < NE) {
        int d = idx_read(ei, NE + e, m);
        if ((unsigned)d < NN) {
            atomicAdd(&g_degw[d], ew[e]);
            atomicAdd(&g_cnt[d], 1);
        }
    }
}

__global__ void k_dinv() {
    int i = blockIdx.x * blockDim.x + threadIdx.x;
    if (i < NN) g_dinv[i] = rsqrtf(fmaxf(g_degw[i] + 1.0f, 1e-12f));
}

// block-local exclusive scan
__global__ void k_scan_block() {
    __shared__ int sh[SCAN_BS];
    int tid = threadIdx.x;
    int i = blockIdx.x * SCAN_BS + tid;
    int v = (i < NN) ? g_cnt[i] : 0;
    sh[tid] = v;
    __syncthreads();
    for (int off = 1; off < SCAN_BS; off <<= 1) {
        int t = (tid >= off) ? sh[tid - off] : 0;
        __syncthreads();
        sh[tid] += t;
        __syncthreads();
    }
    if (i < NN) g_rowptr[i] = sh[tid] - v;       // exclusive
    if (tid == SCAN_BS - 1) g_bsum[blockIdx.x] = sh[tid];
}

__global__ void k_scan_top() {
    if (threadIdx.x == 0 && blockIdx.x == 0) {
        int acc = 0;
        for (int b = 0; b < NB_SCAN; b++) { g_boff[b] = acc; acc += g_bsum[b]; }
        g_rowptr[NN] = acc;
    }
}

__global__ void k_scan_add() {
    int i = blockIdx.x * blockDim.x + threadIdx.x;
    if (i < NN) {
        int r = g_rowptr[i] + g_boff[i >> 10];
        g_rowptr[i] = r;
        g_woff[i] = r;
    }
}

__global__ void k_scatter(const int* __restrict__ ei, const float* __restrict__ ew) {
    int e = blockIdx.x * blockDim.x + threadIdx.x;
    int m = g_mode64;
    if (e < NE) {
        int s = idx_read(ei, e, m);
        int d = idx_read(ei, NE + e, m);
        if ((unsigned)s < NN && (unsigned)d < NN) {
            float w = g_dinv[s] * ew[e] * g_dinv[d];
            int pos = atomicAdd(&g_woff[d], 1);
            g_csr[pos] = make_int2(s, __float_as_int(w));
        }
    }
}

// ---------------- layer 1: aggregate x (16 feats), transform W1 -> sigmoid -> s1 ----------------
__global__ void __launch_bounds__(256) k_layer1(const float* __restrict__ x,
                                                const float* __restrict__ W1,
                                                const float* __restrict__ b1) {
    __shared__ float Wsh[FIN * HID];
    int tid = threadIdx.x;
    for (int i = tid; i < FIN * HID; i += blockDim.x) Wsh[i] = W1[i];
    __syncthreads();

    int lane = tid & 31;
    int gw = (blockIdx.x * blockDim.x + tid) >> 5;
    int tw = (gridDim.x * blockDim.x) >> 5;

    float w0[FIN], w1[FIN];
#pragma unroll
    for (int k = 0; k < FIN; k++) { w0[k] = Wsh[k * HID + lane]; w1[k] = Wsh[k * HID + 32 + lane]; }
    float bb0 = __ldg(b1 + lane), bb1 = __ldg(b1 + 32 + lane);

    int f = lane & 15, half = lane >> 4;
    for (int node = gw; node < NN; node += tw) {
        int beg = g_rowptr[node], end = g_rowptr[node + 1];
        float a = 0.0f;
        for (int e = beg + half; e < end; e += 2) {
            int2 en = g_csr[e];
            a += __int_as_float(en.y) * __ldg(x + (size_t)en.x * FIN + f);
        }
        a += __shfl_xor_sync(0xffffffffu, a, 16);
        float di = g_dinv[node];
        a += di * di * __ldg(x + (size_t)node * FIN + f);

        float o0 = bb0, o1 = bb1;
#pragma unroll
        for (int k = 0; k < FIN; k++) {
            float v = __shfl_sync(0xffffffffu, a, k);
            o0 += v * w0[k]; o1 += v * w1[k];
        }
        g_s1[(size_t)node * HID + lane]      = sigm(o0);
        g_s1[(size_t)node * HID + 32 + lane] = sigm(o1);
    }
}

// ---------------- layer 2: aggregate s1 (64), transform W2 -> sigmoid -> s2 ----------------
__global__ void __launch_bounds__(256) k_layer2(const float* __restrict__ W2,
                                                const float* __restrict__ b2) {
    __shared__ float Wsh[HID * HID];
    int tid = threadIdx.x;
    for (int i = tid; i < HID * HID; i += blockDim.x) Wsh[i] = W2[i];
    __syncthreads();

    int lane = tid & 31;
    int gw = (blockIdx.x * blockDim.x + tid) >> 5;
    int tw = (gridDim.x * blockDim.x) >> 5;

    float w0[HID], w1[HID];
#pragma unroll
    for (int k = 0; k < HID; k++) { w0[k] = Wsh[k * HID + lane]; w1[k] = Wsh[k * HID + 32 + lane]; }
    float bb0 = __ldg(b2 + lane), bb1 = __ldg(b2 + 32 + lane);

    for (int node = gw; node < NN; node += tw) {
        int beg = g_rowptr[node], end = g_rowptr[node + 1];
        float a0 = 0.0f, a1 = 0.0f;
#pragma unroll 4
        for (int e = beg; e < end; e++) {
            int2 en = g_csr[e];
            float w = __int_as_float(en.y);
            const float* row = g_s1 + (size_t)en.x * HID;
            a0 += w * row[lane];
            a1 += w * row[32 + lane];
        }
        float di = g_dinv[node];
        float d2 = di * di;
        const float* srow = g_s1 + (size_t)node * HID;
        a0 += d2 * srow[lane];
        a1 += d2 * srow[32 + lane];

        float o0 = bb0, o1 = bb1;
#pragma unroll
        for (int k = 0; k < 32; k++) {
            float v = __shfl_sync(0xffffffffu, a0, k);
            o0 += v * w0[k]; o1 += v * w1[k];
        }
#pragma unroll
        for (int k = 0; k < 32; k++) {
            float v = __shfl_sync(0xffffffffu, a1, k);
            o0 += v * w0[32 + k]; o1 += v * w1[32 + k];
        }
        g_s2[(size_t)node * HID + lane]      = sigm(o0);
        g_s2[(size_t)node * HID + 32 + lane] = sigm(o1);
    }
}

// ---------------- layer 3: aggregate s2, pool per graph (transform deferred) ----------------
__global__ void __launch_bounds__(256) k_layer3(const int* __restrict__ batch) {
    int tid = threadIdx.x;
    int lane = tid & 31;
    int gw = (blockIdx.x * blockDim.x + tid) >> 5;
    int tw = (gridDim.x * blockDim.x) >> 5;
    int npw = (NN + tw - 1) / tw;
    int start = gw * npw;
    int stop = min(NN, start + npw);
    if (start >= stop) return;
    int m = g_mode64;

    int gcur = -1;
    float p0 = 0.0f, p1 = 0.0f;
    int cnt = 0;

    for (int node = start; node < stop; node++) {
        int beg = g_rowptr[node], end = g_rowptr[node + 1];
        float a0 = 0.0f, a1 = 0.0f;
#pragma unroll 4
        for (int e = beg; e < end; e++) {
            int2 en = g_csr[e];
            float w = __int_as_float(en.y);
            const float* row = g_s2 + (size_t)en.x * HID;
            a0 += w * row[lane];
            a1 += w * row[32 + lane];
        }
        float di = g_dinv[node];
        float d2 = di * di;
        const float* srow = g_s2 + (size_t)node * HID;
        a0 += d2 * srow[lane];
        a1 += d2 * srow[32 + lane];

        int g = idx_read(batch, node, m);
        if ((unsigned)g >= NG) g = 0;
        if (g != gcur) {
            if (gcur >= 0) {
                atomicAdd(&g_gsum[gcur * HID + lane], p0);
                atomicAdd(&g_gsum[gcur * HID + 32 + lane], p1);
                if (lane == 0) atomicAdd(&g_gcnt[gcur], cnt);
            }
            gcur = g; p0 = 0.0f; p1 = 0.0f; cnt = 0;
        }
        p0 += a0; p1 += a1; cnt++;
    }
    if (gcur >= 0) {
        atomicAdd(&g_gsum[gcur * HID + lane], p0);
        atomicAdd(&g_gsum[gcur * HID + 32 + lane], p1);
        if (lane == 0) atomicAdd(&g_gcnt[gcur], cnt);
    }
}

// ---------------- epilogue: mean, W3+b3, Wout+bout ----------------
__global__ void k_epilogue(const float* __restrict__ W3, const float* __restrict__ b3,
                           const float* __restrict__ Wout, const float* __restrict__ bout,
                           float* __restrict__ out) {
    __shared__ float msh[NG][HID + 1];
    int tid = threadIdx.x;
    for (int idx = tid; idx < NG * HID; idx += blockDim.x) {
        int g = idx >> 6, k = idx & 63;
        float c = (float)g_gcnt[g];
        msh[g][k] = g_gsum[idx] / fmaxf(c, 1.0f);
    }
    __syncthreads();
    if (tid < NG) {
        int g = tid;
        float o = __ldg(bout);
        for (int f = 0; f < HID; f++) {
            float h = __ldg(b3 + f);
            float h0 = 0.f, h1 = 0.f, h2 = 0.f, h3 = 0.f;
#pragma unroll 4
            for (int k = 0; k < HID; k += 4) {
                h0 += msh[g][k]     * __ldg(W3 + (k)     * HID + f);
                h1 += msh[g][k + 1] * __ldg(W3 + (k + 1) * HID + f);
                h2 += msh[g][k + 2] * __ldg(W3 + (k + 2) * HID + f);
                h3 += msh[g][k + 3] * __ldg(W3 + (k + 3) * HID + f);
            }
            h += (h0 + h1) + (h2 + h3);
            o += h * __ldg(Wout + f);
        }
        out[g] = o;
    }
}

// ---------------- launch ----------------
extern "C" void kernel_launch(void* const* d_in, const int* in_sizes, int n_in,
                              void* d_out, int out_size) {
    const float* x     = (const float*)d_in[0];
    const int*   ei    = (const int*)d_in[1];     // int32 or int64 (auto-detected)
    const float* ew    = (const float*)d_in[2];
    const int*   batch = (const int*)d_in[3];     // same dtype as edge_index
    const float* W1    = (const float*)d_in[4];
    const float* b1    = (const float*)d_in[5];
    const float* W2    = (const float*)d_in[6];
    const float* b2    = (const float*)d_in[7];
    const float* W3    = (const float*)d_in[8];
    const float* b3    = (const float*)d_in[9];
    const float* Wout  = (const float*)d_in[10];
    const float* bout  = (const float*)d_in[11];
    float* out = (float*)d_out;

    k_probe<<<1, 256>>>(ei);
    k_zero<<<(NN + 255) / 256, 256>>>();
    k_deg<<<(NE + 255) / 256, 256>>>(ei, ew);
    k_dinv<<<(NN + 255) / 256, 256>>>();
    k_scan_block<<<NB_SCAN, SCAN_BS>>>();
    k_scan_top<<<1, 32>>>();
    k_scan_add<<<(NN + 255) / 256, 256>>>();
    k_scatter<<<(NE + 255) / 256, 256>>>(ei, ew);
    k_layer1<<<1024, 256>>>(x, W1, b1);
    k_layer2<<<512, 256>>>(W2, b2);
    k_layer3<<<512, 256>>>(batch);
    k_epilogue<<<1, 256>>>(W3, b3, Wout, bout, out);
}

// round 7
// speedup vs baseline: 1.6392x; 1.6392x over previous
#include <cuda_runtime.h>
#include <cuda_bf16.h>

#define NN      100000
#define NE      3200000
#define FIN     16
#define HID     64
#define NG      64
#define SCAN_BS 1024
#define NB_SCAN ((NN + SCAN_BS - 1) / SCAN_BS)   // 98

// ---------------- scratch (static device memory; no allocations) ----------------
__device__ float g_degw[NN];
__device__ int   g_cnt[NN];
__device__ float g_dinv[NN];
__device__ int   g_rowptr[NN + 1];
__device__ int   g_woff[NN];
__device__ int2  g_csr[NE];            // {src, weight bits}
__device__ float g_bufA[(size_t)NN * HID];   // s1, later s2
__device__ float g_bufB[(size_t)NN * HID];   // agg2
__device__ int   g_bsum[NB_SCAN];
__device__ int   g_boff[NB_SCAN];
__device__ float g_gsum[NG * HID];
__device__ int   g_gcnt[NG];
__device__ int   g_mode64;             // 1 if index tensors are int64, 0 if int32

__device__ __forceinline__ float sigm(float x) { return 1.0f / (1.0f + __expf(-x)); }

__device__ __forceinline__ int idx_read(const int* p, int i, int mode64) {
    return mode64 ? p[2 * i] : p[i];
}

// ---------------- dtype probe ----------------
__global__ void k_probe(const int* __restrict__ ei32) {
    __shared__ int sh[256];
    int tid = threadIdx.x;
    int acc = 0;
    for (int i = tid; i < 4096; i += 256) acc |= ei32[2 * i + 1];
    sh[tid] = acc;
    __syncthreads();
    for (int off = 128; off > 0; off >>= 1) {
        if (tid < off) sh[tid] |= sh[tid + off];
        __syncthreads();
    }
    if (tid == 0) g_mode64 = (sh[0] == 0) ? 1 : 0;
}

// ---------------- setup ----------------
__global__ void k_zero() {
    int i = blockIdx.x * blockDim.x + threadIdx.x;
    if (i < NN) { g_degw[i] = 0.0f; g_cnt[i] = 0; }
    if (i < NG * HID) g_gsum[i] = 0.0f;
    if (i < NG) g_gcnt[i] = 0;
}

__global__ void k_deg(const int* __restrict__ ei, const float* __restrict__ ew) {
    int e = blockIdx.x * blockDim.x + threadIdx.x;
    int m = g_mode64;
    if (e < NE) {
        int d = idx_read(ei, NE + e, m);
        if ((unsigned)d < NN) {
            atomicAdd(&g_degw[d], ew[e]);
            atomicAdd(&g_cnt[d], 1);
        }
    }
}

// block-local exclusive scan (+ dinv computation fused in)
__global__ void k_scan_block() {
    __shared__ int sh[SCAN_BS];
    int tid = threadIdx.x;
    int i = blockIdx.x * SCAN_BS + tid;
    if (i < NN) g_dinv[i] = rsqrtf(fmaxf(g_degw[i] + 1.0f, 1e-12f));
    int v = (i < NN) ? g_cnt[i] : 0;
    sh[tid] = v;
    __syncthreads();
    for (int off = 1; off < SCAN_BS; off <<= 1) {
        int t = (tid >= off) ? sh[tid - off] : 0;
        __syncthreads();
        sh[tid] += t;
        __syncthreads();
    }
    if (i < NN) g_rowptr[i] = sh[tid] - v;       // exclusive
    if (tid == SCAN_BS - 1) g_bsum[blockIdx.x] = sh[tid];
}

__global__ void k_scan_top() {
    if (threadIdx.x == 0 && blockIdx.x == 0) {
        int acc = 0;
        for (int b = 0; b < NB_SCAN; b++) { g_boff[b] = acc; acc += g_bsum[b]; }
        g_rowptr[NN] = acc;
    }
}

__global__ void k_scan_add() {
    int i = blockIdx.x * blockDim.x + threadIdx.x;
    if (i < NN) {
        int r = g_rowptr[i] + g_boff[i >> 10];
        g_rowptr[i] = r;
        g_woff[i] = r;
    }
}

__global__ void k_scatter(const int* __restrict__ ei, const float* __restrict__ ew) {
    int e = blockIdx.x * blockDim.x + threadIdx.x;
    int m = g_mode64;
    if (e < NE) {
        int s = idx_read(ei, e, m);
        int d = idx_read(ei, NE + e, m);
        if ((unsigned)s < NN && (unsigned)d < NN) {
            float w = g_dinv[s] * ew[e] * g_dinv[d];
            int pos = atomicAdd(&g_woff[d], 1);
            g_csr[pos] = make_int2(s, __float_as_int(w));
        }
    }
}

// ---------------- layer 1: aggregate x (16 feats, float4 lanes, 8 edges/iter),
//                  transform W1 -> sigmoid -> g_bufA ----------------
__global__ void __launch_bounds__(256) k_layer1(const float* __restrict__ x,
                                                const float* __restrict__ W1,
                                                const float* __restrict__ b1) {
    __shared__ float Wsh[FIN * HID];
    int tid = threadIdx.x;
    for (int i = tid; i < FIN * HID; i += blockDim.x) Wsh[i] = W1[i];
    __syncthreads();

    int lane = tid & 31;
    int gw = (blockIdx.x * blockDim.x + tid) >> 5;
    int tw = (gridDim.x * blockDim.x) >> 5;

    float w0[FIN], w1[FIN];
#pragma unroll
    for (int k = 0; k < FIN; k++) { w0[k] = Wsh[k * HID + lane]; w1[k] = Wsh[k * HID + 32 + lane]; }
    float bb0 = __ldg(b1 + lane), bb1 = __ldg(b1 + 32 + lane);

    int q = lane & 3;        // which float4 of the 16-float row
    int eo = lane >> 2;      // edge slot 0..7
    int f = lane & 15;       // feature this lane carries into the transform

    for (int node = gw; node < NN; node += tw) {
        int beg = g_rowptr[node], end = g_rowptr[node + 1];
        float ax = 0.f, ay = 0.f, az = 0.f, aw = 0.f;
        for (int e = beg + eo; e < end; e += 8) {
            int2 en = g_csr[e];
            float w = __int_as_float(en.y);
            float4 v = ((const float4*)(x + (size_t)en.x * FIN))[q];
            ax += w * v.x; ay += w * v.y; az += w * v.z; aw += w * v.w;
        }
#pragma unroll
        for (int off = 4; off < 32; off <<= 1) {
            ax += __shfl_xor_sync(0xffffffffu, ax, off);
            ay += __shfl_xor_sync(0xffffffffu, ay, off);
            az += __shfl_xor_sync(0xffffffffu, az, off);
            aw += __shfl_xor_sync(0xffffffffu, aw, off);
        }
        float di = g_dinv[node];
        float d2 = di * di;
        if (lane < 4) {
            float4 s = ((const float4*)(x + (size_t)node * FIN))[lane];
            ax += d2 * s.x; ay += d2 * s.y; az += d2 * s.z; aw += d2 * s.w;
        }
        // redistribute: lane wants feature f, held on lane f>>2, component f&3
        float vx = __shfl_sync(0xffffffffu, ax, f >> 2);
        float vy = __shfl_sync(0xffffffffu, ay, f >> 2);
        float vz = __shfl_sync(0xffffffffu, az, f >> 2);
        float vw = __shfl_sync(0xffffffffu, aw, f >> 2);
        int j = f & 3;
        float a = (j == 0) ? vx : (j == 1) ? vy : (j == 2) ? vz : vw;

        float o0 = bb0, o1 = bb1;
#pragma unroll
        for (int k = 0; k < FIN; k++) {
            float v = __shfl_sync(0xffffffffu, a, k);
            o0 += v * w0[k]; o1 += v * w1[k];
        }
        g_bufA[(size_t)node * HID + lane]      = sigm(o0);
        g_bufA[(size_t)node * HID + 32 + lane] = sigm(o1);
    }
}

// ---------------- pure aggregation (64 feats): g_bufB[n] = sum w*g_bufA[src] + d^2*g_bufA[n] ----
__global__ void __launch_bounds__(256) k_agg_AtoB() {
    const float* in = g_bufA;      // device-side symbol reference (real device address)
    float* out = g_bufB;
    int tid = threadIdx.x;
    int lane = tid & 31;
    int half = lane >> 4;
    int q = lane & 15;                         // float4 index within 64-float row
    int gw = (blockIdx.x * blockDim.x + tid) >> 5;
    int tw = (gridDim.x * blockDim.x) >> 5;

    for (int node = gw; node < NN; node += tw) {
        int beg = g_rowptr[node], end = g_rowptr[node + 1];
        float ax = 0.f, ay = 0.f, az = 0.f, aw = 0.f;
#pragma unroll 2
        for (int e = beg + half; e < end; e += 2) {
            int2 en = g_csr[e];
            float w = __int_as_float(en.y);
            float4 v = ((const float4*)(in + (size_t)en.x * HID))[q];
            ax += w * v.x; ay += w * v.y; az += w * v.z; aw += w * v.w;
        }
        ax += __shfl_xor_sync(0xffffffffu, ax, 16);
        ay += __shfl_xor_sync(0xffffffffu, ay, 16);
        az += __shfl_xor_sync(0xffffffffu, az, 16);
        aw += __shfl_xor_sync(0xffffffffu, aw, 16);
        if (half == 0) {
            float di = g_dinv[node];
            float d2 = di * di;
            float4 s = ((const float4*)(in + (size_t)node * HID))[q];
            ax += d2 * s.x; ay += d2 * s.y; az += d2 * s.z; aw += d2 * s.w;
            ((float4*)(out + (size_t)node * HID))[q] = make_float4(ax, ay, az, aw);
        }
    }
}

// ---------------- dense transform: g_bufA = sigmoid(g_bufB @ W + b), 2 nodes per warp --------
__global__ void __launch_bounds__(256) k_tr_BtoA(const float* __restrict__ W,
                                                 const float* __restrict__ b) {
    const float* in = g_bufB;
    float* out = g_bufA;
    __shared__ float2 Wp[HID][32];             // Wp[k][l] = {W[k][l], W[k][l+32]}
    int tid = threadIdx.x;
    for (int i = tid; i < HID * 32; i += 256) {
        int k = i >> 5, l = i & 31;
        Wp[k][l] = make_float2(W[k * HID + l], W[k * HID + 32 + l]);
    }
    __syncthreads();

    int lane = tid & 31;
    float bb0 = __ldg(b + lane), bb1 = __ldg(b + 32 + lane);
    int gw = (blockIdx.x * blockDim.x + tid) >> 5;
    int tw = (gridDim.x * blockDim.x) >> 5;

    for (int pair = gw; pair < NN / 2; pair += tw) {
        int nA = 2 * pair, nB = nA + 1;
        const float* rA = in + (size_t)nA * HID;
        const float* rB = in + (size_t)nB * HID;
        float r0a = rA[lane], r1a = rA[32 + lane];
        float r0b = rB[lane], r1b = rB[32 + lane];

        float oA0 = bb0, oA1 = bb1, oB0 = bb0, oB1 = bb1;
#pragma unroll
        for (int k = 0; k < 32; k++) {
            float2 wp = Wp[k][lane];
            float va = __shfl_sync(0xffffffffu, r0a, k);
            float vb = __shfl_sync(0xffffffffu, r0b, k);
            oA0 += va * wp.x; oA1 += va * wp.y;
            oB0 += vb * wp.x; oB1 += vb * wp.y;
        }
#pragma unroll
        for (int k = 0; k < 32; k++) {
            float2 wp = Wp[32 + k][lane];
            float va = __shfl_sync(0xffffffffu, r1a, k);
            float vb = __shfl_sync(0xffffffffu, r1b, k);
            oA0 += va * wp.x; oA1 += va * wp.y;
            oB0 += vb * wp.x; oB1 += vb * wp.y;
        }
        float* wA = out + (size_t)nA * HID;
        float* wB = out + (size_t)nB * HID;
        wA[lane] = sigm(oA0); wA[32 + lane] = sigm(oA1);
        wB[lane] = sigm(oB0); wB[32 + lane] = sigm(oB1);
    }
}

// ---------------- layer 3: aggregate g_bufA + pool per graph (transform deferred) ------------
__global__ void __launch_bounds__(256) k_agg3(const int* __restrict__ batch) {
    const float* in = g_bufA;
    int tid = threadIdx.x;
    int lane = tid & 31;
    int half = lane >> 4;
    int q = lane & 15;
    int gw = (blockIdx.x * blockDim.x + tid) >> 5;
    int tw = (gridDim.x * blockDim.x) >> 5;
    int npw = (NN + tw - 1) / tw;
    int start = gw * npw;
    int stop = min(NN, start + npw);
    if (start >= stop) return;
    int m = g_mode64;

    int gcur = -1;
    float px = 0.f, py = 0.f, pz = 0.f, pw = 0.f;
    int cnt = 0;

    for (int node = start; node < stop; node++) {
        int beg = g_rowptr[node], end = g_rowptr[node + 1];
        float ax = 0.f, ay = 0.f, az = 0.f, aw = 0.f;
#pragma unroll 2
        for (int e = beg + half; e < end; e += 2) {
            int2 en = g_csr[e];
            float w = __int_as_float(en.y);
            float4 v = ((const float4*)(in + (size_t)en.x * HID))[q];
            ax += w * v.x; ay += w * v.y; az += w * v.z; aw += w * v.w;
        }
        ax += __shfl_xor_sync(0xffffffffu, ax, 16);
        ay += __shfl_xor_sync(0xffffffffu, ay, 16);
        az += __shfl_xor_sync(0xffffffffu, az, 16);
        aw += __shfl_xor_sync(0xffffffffu, aw, 16);
        float di = g_dinv[node];
        float d2 = di * di;
        float4 s = ((const float4*)(in + (size_t)node * HID))[q];
        ax += d2 * s.x; ay += d2 * s.y; az += d2 * s.z; aw += d2 * s.w;

        int g = idx_read(batch, node, m);
        if ((unsigned)g >= NG) g = 0;
        if (g != gcur) {
            if (gcur >= 0 && half == 0) {
                atomicAdd(&g_gsum[gcur * HID + 4 * q + 0], px);
                atomicAdd(&g_gsum[gcur * HID + 4 * q + 1], py);
                atomicAdd(&g_gsum[gcur * HID + 4 * q + 2], pz);
                atomicAdd(&g_gsum[gcur * HID + 4 * q + 3], pw);
            }
            if (gcur >= 0 && lane == 0) atomicAdd(&g_gcnt[gcur], cnt);
            gcur = g; px = py = pz = pw = 0.f; cnt = 0;
        }
        px += ax; py += ay; pz += az; pw += aw; cnt++;
    }
    if (gcur >= 0 && half == 0) {
        atomicAdd(&g_gsum[gcur * HID + 4 * q + 0], px);
        atomicAdd(&g_gsum[gcur * HID + 4 * q + 1], py);
        atomicAdd(&g_gsum[gcur * HID + 4 * q + 2], pz);
        atomicAdd(&g_gsum[gcur * HID + 4 * q + 3], pw);
    }
    if (gcur >= 0 && lane == 0) atomicAdd(&g_gcnt[gcur], cnt);
}

// ---------------- epilogue: mean, W3+b3, Wout+bout ----------------
__global__ void k_epilogue(const float* __restrict__ W3, const float* __restrict__ b3,
                           const float* __restrict__ Wout, const float* __restrict__ bout,
                           float* __restrict__ out) {
    __shared__ float msh[NG][HID + 1];
    int tid = threadIdx.x;
    for (int idx = tid; idx < NG * HID; idx += blockDim.x) {
        int g = idx >> 6, k = idx & 63;
        float c = (float)g_gcnt[g];
        msh[g][k] = g_gsum[idx] / fmaxf(c, 1.0f);
    }
    __syncthreads();
    if (tid < NG) {
        int g = tid;
        float o = __ldg(bout);
        for (int f = 0; f < HID; f++) {
            float h = __ldg(b3 + f);
            float h0 = 0.f, h1 = 0.f, h2 = 0.f, h3 = 0.f;
#pragma unroll 4
            for (int k = 0; k < HID; k += 4) {
                h0 += msh[g][k]     * __ldg(W3 + (k)     * HID + f);
                h1 += msh[g][k + 1] * __ldg(W3 + (k + 1) * HID + f);
                h2 += msh[g][k + 2] * __ldg(W3 + (k + 2) * HID + f);
                h3 += msh[g][k + 3] * __ldg(W3 + (k + 3) * HID + f);
            }
            h += (h0 + h1) + (h2 + h3);
            o += h * __ldg(Wout + f);
        }
        out[g] = o;
    }
}

// ---------------- launch ----------------
extern "C" void kernel_launch(void* const* d_in, const int* in_sizes, int n_in,
                              void* d_out, int out_size) {
    const float* x     = (const float*)d_in[0];
    const int*   ei    = (const int*)d_in[1];     // int32 or int64 (auto-detected)
    const float* ew    = (const float*)d_in[2];
    const int*   batch = (const int*)d_in[3];
    const float* W1    = (const float*)d_in[4];
    const float* b1    = (const float*)d_in[5];
    const float* W2    = (const float*)d_in[6];
    const float* b2    = (const float*)d_in[7];
    const float* W3    = (const float*)d_in[8];
    const float* b3    = (const float*)d_in[9];
    const float* Wout  = (const float*)d_in[10];
    const float* bout  = (const float*)d_in[11];
    float* out = (float*)d_out;

    k_probe<<<1, 256>>>(ei);
    k_zero<<<(NN + 255) / 256, 256>>>();
    k_deg<<<(NE + 255) / 256, 256>>>(ei, ew);
    k_scan_block<<<NB_SCAN, SCAN_BS>>>();
    k_scan_top<<<1, 32>>>();
    k_scan_add<<<(NN + 255) / 256, 256>>>();
    k_scatter<<<(NE + 255) / 256, 256>>>(ei, ew);
    k_layer1<<<1024, 256>>>(x, W1, b1);     // x -> bufA (s1)
    k_agg_AtoB<<<1024, 256>>>();            // bufA -> bufB (agg2)
    k_tr_BtoA<<<512, 256>>>(W2, b2);        // bufB -> bufA (s2)
    k_agg3<<<512, 256>>>(batch);            // bufA -> pooled sums
    k_epilogue<<<1, 256>>>(W3, b3, Wout, bout, out);
}

// round 8
// speedup vs baseline: 1.8932x; 1.1550x over previous
#include <cuda_runtime.h>
#include <cuda_fp16.h>

#define NN      100000
#define NE      3200000
#define FIN     16
#define HID     64
#define NG      64
#define SCAN_BS 1024
#define NB_SCAN ((NN + SCAN_BS - 1) / SCAN_BS)   // 98

// ---------------- scratch (static device memory; no allocations) ----------------
__device__ float  g_degw[NN];
__device__ int    g_cnt[NN];
__device__ float  g_dinv[NN];
__device__ int    g_rowptr[NN + 1];
__device__ int    g_woff[NN];
__device__ int2   g_csr[NE];                       // {src, weight bits}
__device__ __half g_h1[(size_t)NN * HID];          // s1 (fp16)
__device__ __half g_h2[(size_t)NN * HID];          // s2 (fp16)
__device__ float  g_agg[(size_t)NN * HID];         // agg2 (fp32, streamed)
__device__ int    g_bsum[NB_SCAN];
__device__ float  g_gsum[NG * HID];
__device__ int    g_gcnt[NG];
__device__ int    g_mode64;                        // 1 if index tensors are int64

__device__ __forceinline__ float sigm(float x) { return 1.0f / (1.0f + __expf(-x)); }

__device__ __forceinline__ int idx_read(const int* p, int i, int mode64) {
    return mode64 ? p[2 * i] : p[i];
}

// accumulate 8 fp16 feats (one uint4) into fp32 accumulators with weight w
__device__ __forceinline__ void acc8(float* a, uint4 v, float w) {
    __half2 h0, h1, h2, h3;
    *reinterpret_cast<unsigned*>(&h0) = v.x;
    *reinterpret_cast<unsigned*>(&h1) = v.y;
    *reinterpret_cast<unsigned*>(&h2) = v.z;
    *reinterpret_cast<unsigned*>(&h3) = v.w;
    float2 f0 = __half22float2(h0), f1 = __half22float2(h1);
    float2 f2 = __half22float2(h2), f3 = __half22float2(h3);
    a[0] += w * f0.x; a[1] += w * f0.y;
    a[2] += w * f1.x; a[3] += w * f1.y;
    a[4] += w * f2.x; a[5] += w * f2.y;
    a[6] += w * f3.x; a[7] += w * f3.y;
}

// ---------------- init: dtype probe (block 0) + zeroing (blocks 1..) ----------------
__global__ void k_init(const int* __restrict__ ei32) {
    int tid = threadIdx.x;
    if (blockIdx.x == 0) {
        __shared__ int sh[256];
        int acc = 0;
        for (int i = tid; i < 4096; i += 256) acc |= ei32[2 * i + 1];
        sh[tid] = acc;
        __syncthreads();
        for (int off = 128; off > 0; off >>= 1) {
            if (tid < off) sh[tid] |= sh[tid + off];
            __syncthreads();
        }
        if (tid == 0) g_mode64 = (sh[0] == 0) ? 1 : 0;
        if (tid < NG) g_gcnt[tid] = 0;
    } else {
        int i = (blockIdx.x - 1) * 256 + tid;
        if (i < NN) { g_degw[i] = 0.0f; g_cnt[i] = 0; }
        if (i < NG * HID) g_gsum[i] = 0.0f;
    }
}

__global__ void k_deg(const int* __restrict__ ei, const float* __restrict__ ew) {
    int e = blockIdx.x * blockDim.x + threadIdx.x;
    int m = g_mode64;
    if (e < NE) {
        int d = idx_read(ei, NE + e, m);
        if ((unsigned)d < NN) {
            atomicAdd(&g_degw[d], ew[e]);
            atomicAdd(&g_cnt[d], 1);
        }
    }
}

// block-local exclusive scan (+ dinv fused)
__global__ void k_scan_block() {
    __shared__ int sh[SCAN_BS];
    int tid = threadIdx.x;
    int i = blockIdx.x * SCAN_BS + tid;
    if (i < NN) g_dinv[i] = rsqrtf(fmaxf(g_degw[i] + 1.0f, 1e-12f));
    int v = (i < NN) ? g_cnt[i] : 0;
    sh[tid] = v;
    __syncthreads();
    for (int off = 1; off < SCAN_BS; off <<= 1) {
        int t = (tid >= off) ? sh[tid - off] : 0;
        __syncthreads();
        sh[tid] += t;
        __syncthreads();
    }
    if (i < NN) g_rowptr[i] = sh[tid] - v;       // exclusive, block-local
    if (tid == SCAN_BS - 1) g_bsum[blockIdx.x] = sh[tid];
}

// add per-1024-group offsets; each 256-thread block lies inside one group
__global__ void k_scan_fix() {
    __shared__ int s_off;
    int tid = threadIdx.x;
    int b = blockIdx.x;
    int grp = b >> 2;                            // 1024 = 4 * 256
    if (tid == 0) {
        int acc = 0;
        for (int k = 0; k < grp; k++) acc += g_bsum[k];
        s_off = acc;
        if (b == gridDim.x - 1) {
            int tot = acc;
            for (int k = grp; k < NB_SCAN; k++) tot += g_bsum[k];
            g_rowptr[NN] = tot;
        }
    }
    __syncthreads();
    int i = b * 256 + tid;
    if (i < NN) {
        int r = g_rowptr[i] + s_off;
        g_rowptr[i] = r;
        g_woff[i] = r;
    }
}

__global__ void k_scatter(const int* __restrict__ ei, const float* __restrict__ ew) {
    int e = blockIdx.x * blockDim.x + threadIdx.x;
    int m = g_mode64;
    if (e < NE) {
        int s = idx_read(ei, e, m);
        int d = idx_read(ei, NE + e, m);
        if ((unsigned)s < NN && (unsigned)d < NN) {
            float w = g_dinv[s] * ew[e] * g_dinv[d];
            int pos = atomicAdd(&g_woff[d], 1);
            g_csr[pos] = make_int2(s, __float_as_int(w));
        }
    }
}

// ---------------- layer 1: aggregate x (16 feats), transform W1 -> sigmoid -> g_h1 ----------------
__global__ void __launch_bounds__(256) k_layer1(const float* __restrict__ x,
                                                const float* __restrict__ W1,
                                                const float* __restrict__ b1) {
    __shared__ float Wsh[FIN * HID];
    int tid = threadIdx.x;
    for (int i = tid; i < FIN * HID; i += blockDim.x) Wsh[i] = W1[i];
    __syncthreads();

    int lane = tid & 31;
    int gw = (blockIdx.x * blockDim.x + tid) >> 5;
    int tw = (gridDim.x * blockDim.x) >> 5;

    float w0[FIN], w1[FIN];
#pragma unroll
    for (int k = 0; k < FIN; k++) { w0[k] = Wsh[k * HID + lane]; w1[k] = Wsh[k * HID + 32 + lane]; }
    float bb0 = __ldg(b1 + lane), bb1 = __ldg(b1 + 32 + lane);

    int q = lane & 3;        // which float4 of the 16-float row
    int eo = lane >> 2;      // edge slot 0..7
    int f = lane & 15;       // feature this lane carries into the transform

    for (int node = gw; node < NN; node += tw) {
        int beg = g_rowptr[node], end = g_rowptr[node + 1];
        float ax = 0.f, ay = 0.f, az = 0.f, aw = 0.f;
        for (int e = beg + eo; e < end; e += 8) {
            int2 en = g_csr[e];
            float w = __int_as_float(en.y);
            float4 v = ((const float4*)(x + (size_t)en.x * FIN))[q];
            ax += w * v.x; ay += w * v.y; az += w * v.z; aw += w * v.w;
        }
#pragma unroll
        for (int off = 4; off < 32; off <<= 1) {
            ax += __shfl_xor_sync(0xffffffffu, ax, off);
            ay += __shfl_xor_sync(0xffffffffu, ay, off);
            az += __shfl_xor_sync(0xffffffffu, az, off);
            aw += __shfl_xor_sync(0xffffffffu, aw, off);
        }
        float di = g_dinv[node];
        float d2 = di * di;
        if (lane < 4) {
            float4 s = ((const float4*)(x + (size_t)node * FIN))[lane];
            ax += d2 * s.x; ay += d2 * s.y; az += d2 * s.z; aw += d2 * s.w;
        }
        float vx = __shfl_sync(0xffffffffu, ax, f >> 2);
        float vy = __shfl_sync(0xffffffffu, ay, f >> 2);
        float vz = __shfl_sync(0xffffffffu, az, f >> 2);
        float vw = __shfl_sync(0xffffffffu, aw, f >> 2);
        int j = f & 3;
        float a = (j == 0) ? vx : (j == 1) ? vy : (j == 2) ? vz : vw;

        float o0 = bb0, o1 = bb1;
#pragma unroll
        for (int k = 0; k < FIN; k++) {
            float v = __shfl_sync(0xffffffffu, a, k);
            o0 += v * w0[k]; o1 += v * w1[k];
        }
        g_h1[(size_t)node * HID + lane]      = __float2half(sigm(o0));
        g_h1[(size_t)node * HID + 32 + lane] = __float2half(sigm(o1));
    }
}

// ---------------- agg (fp16 in, fp32 out): g_agg[n] = sum w*g_h1[src] + d^2*g_h1[n] ----------------
// 4 edges in flight per warp iteration; lane j=lane&7 owns 8 features.
__global__ void __launch_bounds__(256) k_agg_h() {
    const __half* in = g_h1;
    float* out = g_agg;
    int tid = threadIdx.x;
    int lane = tid & 31;
    int j = lane & 7;
    int slot = lane >> 3;    // edge slot 0..3
    int gw = (blockIdx.x * blockDim.x + tid) >> 5;
    int tw = (gridDim.x * blockDim.x) >> 5;

    for (int node = gw; node < NN; node += tw) {
        int beg = g_rowptr[node], end = g_rowptr[node + 1];
        float a[8] = {0, 0, 0, 0, 0, 0, 0, 0};
        for (int e = beg + slot; e < end; e += 4) {
            int2 en = g_csr[e];
            float w = __int_as_float(en.y);
            uint4 v = ((const uint4*)(in + (size_t)en.x * HID))[j];
            acc8(a, v, w);
        }
#pragma unroll
        for (int i = 0; i < 8; i++) {
            a[i] += __shfl_xor_sync(0xffffffffu, a[i], 8);
            a[i] += __shfl_xor_sync(0xffffffffu, a[i], 16);
        }
        if (slot == 0) {
            float di = g_dinv[node];
            float d2 = di * di;
            uint4 s = ((const uint4*)(in + (size_t)node * HID))[j];
            acc8(a, s, d2);
            float4* o = (float4*)(out + (size_t)node * HID + j * 8);
            o[0] = make_float4(a[0], a[1], a[2], a[3]);
            o[1] = make_float4(a[4], a[5], a[6], a[7]);
        }
    }
}

// ---------------- dense transform: g_h2 = fp16(sigmoid(g_agg @ W + b)), 2 nodes/warp ----------
__global__ void __launch_bounds__(256) k_tr(const float* __restrict__ W,
                                            const float* __restrict__ b) {
    const float* in = g_agg;
    __half* out = g_h2;
    __shared__ float2 Wp[HID][32];             // Wp[k][l] = {W[k][l], W[k][l+32]}
    int tid = threadIdx.x;
    for (int i = tid; i < HID * 32; i += 256) {
        int k = i >> 5, l = i & 31;
        Wp[k][l] = make_float2(W[k * HID + l], W[k * HID + 32 + l]);
    }
    __syncthreads();

    int lane = tid & 31;
    float bb0 = __ldg(b + lane), bb1 = __ldg(b + 32 + lane);
    int gw = (blockIdx.x * blockDim.x + tid) >> 5;
    int tw = (gridDim.x * blockDim.x) >> 5;

    for (int pair = gw; pair < NN / 2; pair += tw) {
        int nA = 2 * pair, nB = nA + 1;
        const float* rA = in + (size_t)nA * HID;
        const float* rB = in + (size_t)nB * HID;
        float r0a = rA[lane], r1a = rA[32 + lane];
        float r0b = rB[lane], r1b = rB[32 + lane];

        float oA0 = bb0, oA1 = bb1, oB0 = bb0, oB1 = bb1;
#pragma unroll
        for (int k = 0; k < 32; k++) {
            float2 wp = Wp[k][lane];
            float va = __shfl_sync(0xffffffffu, r0a, k);
            float vb = __shfl_sync(0xffffffffu, r0b, k);
            oA0 += va * wp.x; oA1 += va * wp.y;
            oB0 += vb * wp.x; oB1 += vb * wp.y;
        }
#pragma unroll
        for (int k = 0; k < 32; k++) {
            float2 wp = Wp[32 + k][lane];
            float va = __shfl_sync(0xffffffffu, r1a, k);
            float vb = __shfl_sync(0xffffffffu, r1b, k);
            oA0 += va * wp.x; oA1 += va * wp.y;
            oB0 += vb * wp.x; oB1 += vb * wp.y;
        }
        __half* wA = out + (size_t)nA * HID;
        __half* wB = out + (size_t)nB * HID;
        wA[lane] = __float2half(sigm(oA0)); wA[32 + lane] = __float2half(sigm(oA1));
        wB[lane] = __float2half(sigm(oB0)); wB[32 + lane] = __float2half(sigm(oB1));
    }
}

// ---------------- layer 3: aggregate g_h2 + pool per graph (transform deferred) ------------
__global__ void __launch_bounds__(256) k_agg3(const int* __restrict__ batch) {
    const __half* in = g_h2;
    int tid = threadIdx.x;
    int lane = tid & 31;
    int j = lane & 7;
    int slot = lane >> 3;
    int gw = (blockIdx.x * blockDim.x + tid) >> 5;
    int tw = (gridDim.x * blockDim.x) >> 5;
    int npw = (NN + tw - 1) / tw;
    int start = gw * npw;
    int stop = min(NN, start + npw);
    if (start >= stop) return;
    int m = g_mode64;

    int gcur = -1;
    float p[8] = {0, 0, 0, 0, 0, 0, 0, 0};
    int cnt = 0;

    for (int node = start; node < stop; node++) {
        int beg = g_rowptr[node], end = g_rowptr[node + 1];
        float a[8] = {0, 0, 0, 0, 0, 0, 0, 0};
        for (int e = beg + slot; e < end; e += 4) {
            int2 en = g_csr[e];
            float w = __int_as_float(en.y);
            uint4 v = ((const uint4*)(in + (size_t)en.x * HID))[j];
            acc8(a, v, w);
        }
#pragma unroll
        for (int i = 0; i < 8; i++) {
            a[i] += __shfl_xor_sync(0xffffffffu, a[i], 8);
            a[i] += __shfl_xor_sync(0xffffffffu, a[i], 16);
        }

        int g = idx_read(batch, node, m);
        if ((unsigned)g >= NG) g = 0;
        if (g != gcur) {
            if (gcur >= 0 && slot == 0) {
#pragma unroll
                for (int i = 0; i < 8; i++)
                    atomicAdd(&g_gsum[gcur * HID + j * 8 + i], p[i]);
            }
            if (gcur >= 0 && lane == 0) atomicAdd(&g_gcnt[gcur], cnt);
            gcur = g;
#pragma unroll
            for (int i = 0; i < 8; i++) p[i] = 0.f;
            cnt = 0;
        }
        if (slot == 0) {
            float di = g_dinv[node];
            float d2 = di * di;
            uint4 s = ((const uint4*)(in + (size_t)node * HID))[j];
            acc8(a, s, d2);
#pragma unroll
            for (int i = 0; i < 8; i++) p[i] += a[i];
        }
        cnt++;
    }
    if (gcur >= 0 && slot == 0) {
#pragma unroll
        for (int i = 0; i < 8; i++)
            atomicAdd(&g_gsum[gcur * HID + j * 8 + i], p[i]);
    }
    if (gcur >= 0 && lane == 0) atomicAdd(&g_gcnt[gcur], cnt);
}

// ---------------- epilogue: mean, W3+b3, Wout+bout ----------------
__global__ void k_epilogue(const float* __restrict__ W3, const float* __restrict__ b3,
                           const float* __restrict__ Wout, const float* __restrict__ bout,
                           float* __restrict__ out) {
    __shared__ float msh[NG][HID + 1];
    int tid = threadIdx.x;
    for (int idx = tid; idx < NG * HID; idx += blockDim.x) {
        int g = idx >> 6, k = idx & 63;
        float c = (float)g_gcnt[g];
        msh[g][k] = g_gsum[idx] / fmaxf(c, 1.0f);
    }
    __syncthreads();
    if (tid < NG) {
        int g = tid;
        float o = __ldg(bout);
        for (int f = 0; f < HID; f++) {
            float h = __ldg(b3 + f);
            float h0 = 0.f, h1 = 0.f, h2 = 0.f, h3 = 0.f;
#pragma unroll 4
            for (int k = 0; k < HID; k += 4) {
                h0 += msh[g][k]     * __ldg(W3 + (k)     * HID + f);
                h1 += msh[g][k + 1] * __ldg(W3 + (k + 1) * HID + f);
                h2 += msh[g][k + 2] * __ldg(W3 + (k + 2) * HID + f);
                h3 += msh[g][k + 3] * __ldg(W3 + (k + 3) * HID + f);
            }
            h += (h0 + h1) + (h2 + h3);
            o += h * __ldg(Wout + f);
        }
        out[g] = o;
    }
}

// ---------------- launch ----------------
extern "C" void kernel_launch(void* const* d_in, const int* in_sizes, int n_in,
                              void* d_out, int out_size) {
    const float* x     = (const float*)d_in[0];
    const int*   ei    = (const int*)d_in[1];     // int32 or int64 (auto-detected)
    const float* ew    = (const float*)d_in[2];
    const int*   batch = (const int*)d_in[3];
    const float* W1    = (const float*)d_in[4];
    const float* b1    = (const float*)d_in[5];
    const float* W2    = (const float*)d_in[6];
    const float* b2    = (const float*)d_in[7];
    const float* W3    = (const float*)d_in[8];
    const float* b3    = (const float*)d_in[9];
    const float* Wout  = (const float*)d_in[10];
    const float* bout  = (const float*)d_in[11];
    float* out = (float*)d_out;

    k_init<<<(NN + 255) / 256 + 1, 256>>>(ei);
    k_deg<<<(NE + 255) / 256, 256>>>(ei, ew);
    k_scan_block<<<NB_SCAN, SCAN_BS>>>();
    k_scan_fix<<<(NN + 255) / 256, 256>>>();
    k_scatter<<<(NE + 255) / 256, 256>>>(ei, ew);
    k_layer1<<<1024, 256>>>(x, W1, b1);     // x -> h1 (s1, fp16)
    k_agg_h<<<1024, 256>>>();               // h1 -> agg (fp32)
    k_tr<<<512, 256>>>(W2, b2);             // agg -> h2 (s2, fp16)
    k_agg3<<<512, 256>>>(batch);            // h2 -> pooled sums
    k_epilogue<<<1, 256>>>(W3, b3, Wout, bout, out);
}

// round 9
// speedup vs baseline: 1.9147x; 1.0113x over previous
#include <cuda_runtime.h>
#include <cuda_fp16.h>

#define NN      100000
#define NE      3200000
#define FIN     16
#define HID     64
#define NG      64
#define SCAN_BS 1024
#define NB_SCAN ((NN + SCAN_BS - 1) / SCAN_BS)   // 98

// ---------------- scratch (static device memory; no allocations) ----------------
__device__ float  g_degw[NN];
__device__ int    g_cnt[NN];
__device__ float  g_dinv[NN];
__device__ int    g_rowptr[NN + 1];
__device__ int    g_woff[NN];
__device__ int2   g_csr[NE];                       // {src, weight bits}
__device__ __half g_xh[(size_t)NN * FIN];          // fp16 copy of x
__device__ __half g_h1[(size_t)NN * HID];          // s1 (fp16)
__device__ __half g_h2[(size_t)NN * HID];          // s2 (fp16)
__device__ float  g_agg[(size_t)NN * HID];         // agg2 (fp32)
__device__ int    g_pub[NB_SCAN];                  // lookback: (partial<<1)|1
__device__ float  g_gsum[NG * HID];
__device__ int    g_gcnt[NG];
__device__ int    g_mode64;                        // 1 if index tensors are int64

__device__ __forceinline__ float sigm(float x) { return 1.0f / (1.0f + __expf(-x)); }

__device__ __forceinline__ int idx_read(const int* p, int i, int mode64) {
    return mode64 ? p[2 * i] : p[i];
}

// accumulate 8 fp16 feats (one uint4) into fp32 accumulators with weight w
__device__ __forceinline__ void acc8(float* a, uint4 v, float w) {
    __half2 h0, h1, h2, h3;
    *reinterpret_cast<unsigned*>(&h0) = v.x;
    *reinterpret_cast<unsigned*>(&h1) = v.y;
    *reinterpret_cast<unsigned*>(&h2) = v.z;
    *reinterpret_cast<unsigned*>(&h3) = v.w;
    float2 f0 = __half22float2(h0), f1 = __half22float2(h1);
    float2 f2 = __half22float2(h2), f3 = __half22float2(h3);
    a[0] += w * f0.x; a[1] += w * f0.y;
    a[2] += w * f1.x; a[3] += w * f1.y;
    a[4] += w * f2.x; a[5] += w * f2.y;
    a[6] += w * f3.x; a[7] += w * f3.y;
}

// 4 fp16 feats (uint2) -> 4 floats accumulated
__device__ __forceinline__ void acc4(float& ax, float& ay, float& az, float& aw,
                                     uint2 v, float w) {
    __half2 h0, h1;
    *reinterpret_cast<unsigned*>(&h0) = v.x;
    *reinterpret_cast<unsigned*>(&h1) = v.y;
    float2 f0 = __half22float2(h0), f1 = __half22float2(h1);
    ax += w * f0.x; ay += w * f0.y; az += w * f1.x; aw += w * f1.y;
}

// ---------------- [0] init: probe dtype, zero scratch, convert x -> fp16 ----------------
__global__ void k_pre(const int* __restrict__ ei32, const float* __restrict__ x) {
    int tid = threadIdx.x;
    int gi = blockIdx.x * 256 + tid;
    if (blockIdx.x == 0 && tid < 32) {
        // warp 0 probe: 64 odd words; all-zero <=> int64 (ids < 2^31)
        int acc = ei32[2 * tid + 1] | ei32[2 * (tid + 32) + 1];
#pragma unroll
        for (int off = 16; off > 0; off >>= 1) acc |= __shfl_xor_sync(0xffffffffu, acc, off);
        if (tid == 0) g_mode64 = (acc == 0) ? 1 : 0;
    }
    if (gi < NN) { g_degw[gi] = 0.0f; g_cnt[gi] = 0; }
    if (gi < NG * HID) g_gsum[gi] = 0.0f;
    if (gi < NG) g_gcnt[gi] = 0;
    if (gi < NB_SCAN) g_pub[gi] = 0;
    // convert x (NN*FIN floats) to fp16, 2 per thread
    int ci = gi * 2;
    if (ci + 1 < NN * FIN) {
        float2 v = *(const float2*)(x + ci);
        *(__half2*)(g_xh + ci) = __floats2half2_rn(v.x, v.y);
    }
}

// ---------------- [1] degree count + weighted degree ----------------
__global__ void k_deg(const int* __restrict__ ei, const float* __restrict__ ew) {
    int e = blockIdx.x * blockDim.x + threadIdx.x;
    int m = g_mode64;
    if (e < NE) {
        int d = idx_read(ei, NE + e, m);
        if ((unsigned)d < NN) {
            atomicAdd(&g_degw[d], ew[e]);
            atomicAdd(&g_cnt[d], 1);
        }
    }
}

// ---------------- [2] single-kernel scan (decoupled lookback) + dinv ----------------
__global__ void __launch_bounds__(SCAN_BS) k_scan() {
    __shared__ int sh[SCAN_BS];
    __shared__ int s_off;
    int tid = threadIdx.x;
    int bid = blockIdx.x;
    int i = bid * SCAN_BS + tid;
    if (i < NN) g_dinv[i] = rsqrtf(fmaxf(g_degw[i] + 1.0f, 1e-12f));
    int v = (i < NN) ? g_cnt[i] : 0;
    sh[tid] = v;
    __syncthreads();
    for (int off = 1; off < SCAN_BS; off <<= 1) {
        int t = (tid >= off) ? sh[tid - off] : 0;
        __syncthreads();
        sh[tid] += t;
        __syncthreads();
    }
    // publish this block's partial (packed with ready bit; single word => no fence needed)
    if (tid == 0) atomicExch(&g_pub[bid], (sh[SCAN_BS - 1] << 1) | 1);
    // warp 0 gathers all predecessors' partials
    if (tid < 32) {
        int acc = 0;
        for (int k = tid; k < bid; k += 32) {
            int p;
            do { p = atomicOr(&g_pub[k], 0); } while ((p & 1) == 0);
            acc += p >> 1;
        }
#pragma unroll
        for (int off = 16; off > 0; off >>= 1) acc += __shfl_xor_sync(0xffffffffu, acc, off);
        if (tid == 0) s_off = acc;
    }
    __syncthreads();
    int off = s_off;
    if (i < NN) {
        int r = off + sh[tid] - v;     // exclusive prefix
        g_rowptr[i] = r;
        g_woff[i] = r;
    }
    if (bid == NB_SCAN - 1 && tid == SCAN_BS - 1) g_rowptr[NN] = off + sh[tid];
}

// ---------------- [3] CSR scatter (PROFILED SLOT) ----------------
__global__ void k_scatter(const int* __restrict__ ei, const float* __restrict__ ew) {
    int e = blockIdx.x * blockDim.x + threadIdx.x;
    int m = g_mode64;
    if (e < NE) {
        int s = idx_read(ei, e, m);
        int d = idx_read(ei, NE + e, m);
        if ((unsigned)s < NN && (unsigned)d < NN) {
            float w = g_dinv[s] * ew[e] * g_dinv[d];
            int pos = atomicAdd(&g_woff[d], 1);
            g_csr[pos] = make_int2(s, __float_as_int(w));
        }
    }
}

// ---------------- [4] layer 1: aggregate fp16 x (16 feats), transform W1 -> sigmoid -> g_h1 ----
__global__ void __launch_bounds__(256) k_layer1(const float* __restrict__ W1,
                                                const float* __restrict__ b1) {
    __shared__ float Wsh[FIN * HID];
    int tid = threadIdx.x;
    for (int i = tid; i < FIN * HID; i += blockDim.x) Wsh[i] = W1[i];
    __syncthreads();

    int lane = tid & 31;
    int gw = (blockIdx.x * blockDim.x + tid) >> 5;
    int tw = (gridDim.x * blockDim.x) >> 5;

    float w0[FIN], w1[FIN];
#pragma unroll
    for (int k = 0; k < FIN; k++) { w0[k] = Wsh[k * HID + lane]; w1[k] = Wsh[k * HID + 32 + lane]; }
    float bb0 = __ldg(b1 + lane), bb1 = __ldg(b1 + 32 + lane);

    int q = lane & 3;        // which uint2 (4 feats) of the 16-feat fp16 row
    int eo = lane >> 2;      // edge slot 0..7
    int f = lane & 15;       // feature this lane carries into the transform

    for (int node = gw; node < NN; node += tw) {
        int beg = g_rowptr[node], end = g_rowptr[node + 1];
        float ax = 0.f, ay = 0.f, az = 0.f, aw = 0.f;
        for (int e = beg + eo; e < end; e += 8) {
            int2 en = g_csr[e];
            float w = __int_as_float(en.y);
            uint2 v = ((const uint2*)(g_xh + (size_t)en.x * FIN))[q];
            acc4(ax, ay, az, aw, v, w);
        }
#pragma unroll
        for (int off = 4; off < 32; off <<= 1) {
            ax += __shfl_xor_sync(0xffffffffu, ax, off);
            ay += __shfl_xor_sync(0xffffffffu, ay, off);
            az += __shfl_xor_sync(0xffffffffu, az, off);
            aw += __shfl_xor_sync(0xffffffffu, aw, off);
        }
        float di = g_dinv[node];
        float d2 = di * di;
        if (lane < 4) {
            uint2 s = ((const uint2*)(g_xh + (size_t)node * FIN))[lane];
            acc4(ax, ay, az, aw, s, d2);
        }
        float vx = __shfl_sync(0xffffffffu, ax, f >> 2);
        float vy = __shfl_sync(0xffffffffu, ay, f >> 2);
        float vz = __shfl_sync(0xffffffffu, az, f >> 2);
        float vw = __shfl_sync(0xffffffffu, aw, f >> 2);
        int j = f & 3;
        float a = (j == 0) ? vx : (j == 1) ? vy : (j == 2) ? vz : vw;

        float o0 = bb0, o1 = bb1;
#pragma unroll
        for (int k = 0; k < FIN; k++) {
            float v = __shfl_sync(0xffffffffu, a, k);
            o0 += v * w0[k]; o1 += v * w1[k];
        }
        g_h1[(size_t)node * HID + lane]      = __float2half(sigm(o0));
        g_h1[(size_t)node * HID + 32 + lane] = __float2half(sigm(o1));
    }
}

// ---------------- [5] agg (fp16 in, fp32 out), 2-edge pipelined ----------------
__global__ void __launch_bounds__(256) k_agg_h() {
    const __half* in = g_h1;
    float* out = g_agg;
    int tid = threadIdx.x;
    int lane = tid & 31;
    int j = lane & 7;
    int slot = lane >> 3;    // edge slot 0..3
    int gw = (blockIdx.x * blockDim.x + tid) >> 5;
    int tw = (gridDim.x * blockDim.x) >> 5;

    for (int node = gw; node < NN; node += tw) {
        int beg = g_rowptr[node], end = g_rowptr[node + 1];
        float a[8] = {0, 0, 0, 0, 0, 0, 0, 0};
        int e = beg + slot;
        for (; e + 4 < end; e += 8) {
            int2 en0 = g_csr[e];
            int2 en1 = g_csr[e + 4];
            uint4 v0 = ((const uint4*)(in + (size_t)en0.x * HID))[j];
            uint4 v1 = ((const uint4*)(in + (size_t)en1.x * HID))[j];
            acc8(a, v0, __int_as_float(en0.y));
            acc8(a, v1, __int_as_float(en1.y));
        }
        if (e < end) {
            int2 en = g_csr[e];
            uint4 v = ((const uint4*)(in + (size_t)en.x * HID))[j];
            acc8(a, v, __int_as_float(en.y));
        }
#pragma unroll
        for (int i = 0; i < 8; i++) {
            a[i] += __shfl_xor_sync(0xffffffffu, a[i], 8);
            a[i] += __shfl_xor_sync(0xffffffffu, a[i], 16);
        }
        if (slot == 0) {
            float di = g_dinv[node];
            float d2 = di * di;
            uint4 s = ((const uint4*)(in + (size_t)node * HID))[j];
            acc8(a, s, d2);
            float4* o = (float4*)(out + (size_t)node * HID + j * 8);
            o[0] = make_float4(a[0], a[1], a[2], a[3]);
            o[1] = make_float4(a[4], a[5], a[6], a[7]);
        }
    }
}

// ---------------- [6] dense transform: g_h2 = fp16(sigmoid(g_agg @ W + b)) ----------------
__global__ void __launch_bounds__(256) k_tr(const float* __restrict__ W,
                                            const float* __restrict__ b) {
    const float* in = g_agg;
    __half* out = g_h2;
    __shared__ float2 Wp[HID][32];
    int tid = threadIdx.x;
    for (int i = tid; i < HID * 32; i += 256) {
        int k = i >> 5, l = i & 31;
        Wp[k][l] = make_float2(W[k * HID + l], W[k * HID + 32 + l]);
    }
    __syncthreads();

    int lane = tid & 31;
    float bb0 = __ldg(b + lane), bb1 = __ldg(b + 32 + lane);
    int gw = (blockIdx.x * blockDim.x + tid) >> 5;
    int tw = (gridDim.x * blockDim.x) >> 5;

    for (int pair = gw; pair < NN / 2; pair += tw) {
        int nA = 2 * pair, nB = nA + 1;
        const float* rA = in + (size_t)nA * HID;
        const float* rB = in + (size_t)nB * HID;
        float r0a = rA[lane], r1a = rA[32 + lane];
        float r0b = rB[lane], r1b = rB[32 + lane];

        float oA0 = bb0, oA1 = bb1, oB0 = bb0, oB1 = bb1;
#pragma unroll
        for (int k = 0; k < 32; k++) {
            float2 wp = Wp[k][lane];
            float va = __shfl_sync(0xffffffffu, r0a, k);
            float vb = __shfl_sync(0xffffffffu, r0b, k);
            oA0 += va * wp.x; oA1 += va * wp.y;
            oB0 += vb * wp.x; oB1 += vb * wp.y;
        }
#pragma unroll
        for (int k = 0; k < 32; k++) {
            float2 wp = Wp[32 + k][lane];
            float va = __shfl_sync(0xffffffffu, r1a, k);
            float vb = __shfl_sync(0xffffffffu, r1b, k);
            oA0 += va * wp.x; oA1 += va * wp.y;
            oB0 += vb * wp.x; oB1 += vb * wp.y;
        }
        __half* wA = out + (size_t)nA * HID;
        __half* wB = out + (size_t)nB * HID;
        wA[lane] = __float2half(sigm(oA0)); wA[32 + lane] = __float2half(sigm(oA1));
        wB[lane] = __float2half(sigm(oB0)); wB[32 + lane] = __float2half(sigm(oB1));
    }
}

// ---------------- [7] layer 3: aggregate g_h2 + pool per graph ----------------
__global__ void __launch_bounds__(256) k_agg3(const int* __restrict__ batch) {
    const __half* in = g_h2;
    int tid = threadIdx.x;
    int lane = tid & 31;
    int j = lane & 7;
    int slot = lane >> 3;
    int gw = (blockIdx.x * blockDim.x + tid) >> 5;
    int tw = (gridDim.x * blockDim.x) >> 5;
    int npw = (NN + tw - 1) / tw;
    int start = gw * npw;
    int stop = min(NN, start + npw);
    if (start >= stop) return;
    int m = g_mode64;

    int gcur = -1;
    float p[8] = {0, 0, 0, 0, 0, 0, 0, 0};
    int cnt = 0;

    for (int node = start; node < stop; node++) {
        int beg = g_rowptr[node], end = g_rowptr[node + 1];
        float a[8] = {0, 0, 0, 0, 0, 0, 0, 0};
        int e = beg + slot;
        for (; e + 4 < end; e += 8) {
            int2 en0 = g_csr[e];
            int2 en1 = g_csr[e + 4];
            uint4 v0 = ((const uint4*)(in + (size_t)en0.x * HID))[j];
            uint4 v1 = ((const uint4*)(in + (size_t)en1.x * HID))[j];
            acc8(a, v0, __int_as_float(en0.y));
            acc8(a, v1, __int_as_float(en1.y));
        }
        if (e < end) {
            int2 en = g_csr[e];
            uint4 v = ((const uint4*)(in + (size_t)en.x * HID))[j];
            acc8(a, v, __int_as_float(en.y));
        }
#pragma unroll
        for (int i = 0; i < 8; i++) {
            a[i] += __shfl_xor_sync(0xffffffffu, a[i], 8);
            a[i] += __shfl_xor_sync(0xffffffffu, a[i], 16);
        }

        int g = idx_read(batch, node, m);
        if ((unsigned)g >= NG) g = 0;
        if (g != gcur) {
            if (gcur >= 0 && slot == 0) {
#pragma unroll
                for (int i = 0; i < 8; i++)
                    atomicAdd(&g_gsum[gcur * HID + j * 8 + i], p[i]);
            }
            if (gcur >= 0 && lane == 0) atomicAdd(&g_gcnt[gcur], cnt);
            gcur = g;
#pragma unroll
            for (int i = 0; i < 8; i++) p[i] = 0.f;
            cnt = 0;
        }
        if (slot == 0) {
            float di = g_dinv[node];
            float d2 = di * di;
            uint4 s = ((const uint4*)(in + (size_t)node * HID))[j];
            acc8(a, s, d2);
#pragma unroll
            for (int i = 0; i < 8; i++) p[i] += a[i];
        }
        cnt++;
    }
    if (gcur >= 0 && slot == 0) {
#pragma unroll
        for (int i = 0; i < 8; i++)
            atomicAdd(&g_gsum[gcur * HID + j * 8 + i], p[i]);
    }
    if (gcur >= 0 && lane == 0) atomicAdd(&g_gcnt[gcur], cnt);
}

// ---------------- [8] epilogue: mean, W3+b3, Wout+bout ----------------
__global__ void k_epilogue(const float* __restrict__ W3, const float* __restrict__ b3,
                           const float* __restrict__ Wout, const float* __restrict__ bout,
                           float* __restrict__ out) {
    __shared__ float msh[NG][HID + 1];
    int tid = threadIdx.x;
    for (int idx = tid; idx < NG * HID; idx += blockDim.x) {
        int g = idx >> 6, k = idx & 63;
        float c = (float)g_gcnt[g];
        msh[g][k] = g_gsum[idx] / fmaxf(c, 1.0f);
    }
    __syncthreads();
    if (tid < NG) {
        int g = tid;
        float o = __ldg(bout);
        for (int f = 0; f < HID; f++) {
            float h = __ldg(b3 + f);
            float h0 = 0.f, h1 = 0.f, h2 = 0.f, h3 = 0.f;
#pragma unroll 4
            for (int k = 0; k < HID; k += 4) {
                h0 += msh[g][k]     * __ldg(W3 + (k)     * HID + f);
                h1 += msh[g][k + 1] * __ldg(W3 + (k + 1) * HID + f);
                h2 += msh[g][k + 2] * __ldg(W3 + (k + 2) * HID + f);
                h3 += msh[g][k + 3] * __ldg(W3 + (k + 3) * HID + f);
            }
            h += (h0 + h1) + (h2 + h3);
            o += h * __ldg(Wout + f);
        }
        out[g] = o;
    }
}

// ---------------- launch ----------------
extern "C" void kernel_launch(void* const* d_in, const int* in_sizes, int n_in,
                              void* d_out, int out_size) {
    const float* x     = (const float*)d_in[0];
    const int*   ei    = (const int*)d_in[1];     // int32 or int64 (auto-detected)
    const float* ew    = (const float*)d_in[2];
    const int*   batch = (const int*)d_in[3];
    const float* W1    = (const float*)d_in[4];
    const float* b1    = (const float*)d_in[5];
    const float* W2    = (const float*)d_in[6];
    const float* b2    = (const float*)d_in[7];
    const float* W3    = (const float*)d_in[8];
    const float* b3    = (const float*)d_in[9];
    const float* Wout  = (const float*)d_in[10];
    const float* bout  = (const float*)d_in[11];
    float* out = (float*)d_out;

    int pre_blocks = (NN * FIN / 2 + 255) / 256;          // covers conversion + zeroing
    k_pre<<<pre_blocks, 256>>>(ei, x);                    // [0]
    k_deg<<<(NE + 255) / 256, 256>>>(ei, ew);             // [1]
    k_scan<<<NB_SCAN, SCAN_BS>>>();                       // [2]
    k_scatter<<<(NE + 255) / 256, 256>>>(ei, ew);         // [3] <- profiled slot
    k_layer1<<<1024, 256>>>(W1, b1);                      // [4] xh -> h1
    k_agg_h<<<1024, 256>>>();                             // [5] h1 -> agg
    k_tr<<<512, 256>>>(W2, b2);                           // [6] agg -> h2
    k_agg3<<<512, 256>>>(batch);                          // [7] h2 -> pooled
    k_epilogue<<<1, 256>>>(W3, b3, Wout, bout, out);      // [8]
}